// round 9
// baseline (speedup 1.0000x reference)
#include <cuda_runtime.h>

// Laplacian pyramid, 5 levels, (16,3,1024,1024) fp32, edge-clamp padding.
// Fused per level: reduce (5x5 binomial, stride 2) + laplacian (fine - expand(coarse)).
// Block (18, TCY/2+2): interior threads make the TCYx64 coarse tile (2x4 each);
// border ring computes the coarse halo with the SAME vectorized path. Stage 2
// re-reads its 2x8 fine blocks from global (L1-resident) instead of register
// staging, freeing ~32 regs/thread for 4 CTAs/SM occupancy.

#define NIMG 48  // 16 * 3

__device__ float g_g1[NIMG * 512 * 512];
__device__ float g_g2[NIMG * 256 * 256];
__device__ float g_g3[NIMG * 128 * 128];

template <int Hc, int Wc, int TCY>
__global__ __launch_bounds__(18 * (TCY / 2 + 2), 4) void fused_level_kernel(
    const float* __restrict__ fine,
    float* __restrict__ coarse_out,
    float* __restrict__ lap_out)
{
    constexpr int H = 2 * Hc, W = 2 * Wc;
    constexpr int TCX = 64;                    // inner coarse tile width
    constexpr int IY = TCY / 2;                // inner thread rows
    __shared__ float sc[TCY + 4][73];

    const int gx = threadIdx.x;                // 0..17 (4 coarse cols each)
    const int iy = threadIdx.y;                // 0..IY+1 (2 coarse rows each)
    const int img = blockIdx.z;
    const int c0y = blockIdx.y * TCY;
    const int c0x = blockIdx.x * TCX;
    const int ci0 = c0y + 2 * (iy - 1);        // may be -2 or Hc (halo threads)
    const int cj0 = c0x + 4 * (gx - 1);        // may be -4 or Wc (halo threads)

    // clamped compute coordinates
    const int ci0c = ci0 < 0 ? 0 : (ci0 > Hc - 2 ? Hc - 2 : ci0);
    const int cj0c = cj0 < 0 ? 0 : (cj0 > Wc - 4 ? Wc - 4 : cj0);
    const bool topE   = (ci0 < 0);
    const bool botE   = (ci0 > Hc - 2);
    const bool lColE  = (cj0 < 0);
    const bool rColE  = (cj0 > Wc - 4);

    const float* fp = fine + (size_t)img * H * W;
    const bool leftE  = (cj0c == 0);
    const bool rightE = (cj0c == Wc - 4);
    const int cbase = 2 * cj0c - 4;            // float4-aligned fine col base

    const float hw0 = 0.0625f, hw1 = 0.25f, hw2 = 0.375f;
    const float hwv[5] = {hw0, hw1, hw2, hw1, hw0};

    float acc0[4] = {0.f, 0.f, 0.f, 0.f};      // coarse row ci0c
    float acc1[4] = {0.f, 0.f, 0.f, 0.f};      // coarse row ci0c+1

    // ---- stage 1: reduce — 7 fine rows cover both coarse rows ----
#pragma unroll
    for (int a = 0; a < 7; a++) {
        int r = 2 * ci0c - 2 + a;
        r = r < 0 ? 0 : (r >= H ? H - 1 : r);
        const float* rp = fp + (size_t)r * W;

        float buf[16];
        if (!leftE) {
            float4 q = *(const float4*)(rp + cbase);
            buf[0] = q.x; buf[1] = q.y; buf[2] = q.z; buf[3] = q.w;
        }
        {
            float4 q = *(const float4*)(rp + cbase + 4);
            buf[4] = q.x; buf[5] = q.y; buf[6] = q.z; buf[7] = q.w;
            float4 p = *(const float4*)(rp + cbase + 8);
            buf[8] = p.x; buf[9] = p.y; buf[10] = p.z; buf[11] = p.w;
        }
        if (!rightE) {
            float4 q = *(const float4*)(rp + cbase + 12);
            buf[12] = q.x; buf[13] = q.y; buf[14] = q.z; buf[15] = q.w;
        } else {
            buf[12] = buf[11];                 // clamp col W -> W-1
        }
        if (leftE) { buf[2] = buf[4]; buf[3] = buf[4]; }  // clamp cols -2,-1 -> 0

        float hv[4];
#pragma unroll
        for (int t = 0; t < 4; t++) {
            hv[t] = fmaf(hw0, buf[2 + 2 * t] + buf[6 + 2 * t],
                    fmaf(hw1, buf[3 + 2 * t] + buf[5 + 2 * t],
                         hw2 * buf[4 + 2 * t]));
        }
        if (a < 5) {
            float w = hwv[a];
#pragma unroll
            for (int t = 0; t < 4; t++) acc0[t] = fmaf(w, hv[t], acc0[t]);
        }
        if (a >= 2) {
            float w = hwv[a - 2];
#pragma unroll
            for (int t = 0; t < 4; t++) acc1[t] = fmaf(w, hv[t], acc1[t]);
        }
    }

    // column-edge groups: every stored col clamps to the same coarse col
    if (lColE) {
        acc0[1] = acc0[0]; acc0[2] = acc0[0]; acc0[3] = acc0[0];
        acc1[1] = acc1[0]; acc1[2] = acc1[0]; acc1[3] = acc1[0];
    }
    if (rColE) {
        acc0[0] = acc0[3]; acc0[1] = acc0[3]; acc0[2] = acc0[3];
        acc1[0] = acc1[3]; acc1[1] = acc1[3]; acc1[2] = acc1[3];
    }

    // stage into SMEM (row-edge threads broadcast the clamped row)
    {
        const int sr = 2 * iy, scl = 4 * gx;
#pragma unroll
        for (int t = 0; t < 4; t++) {
            float v0 = topE ? acc0[t] : (botE ? acc1[t] : acc0[t]);
            float v1 = topE ? acc0[t] : acc1[t];
            sc[sr][scl + t] = v0;
            sc[sr + 1][scl + t] = v1;
        }
    }

    const bool inner = (iy >= 1) && (iy <= IY) && (gx >= 1) && (gx <= 16);

    // write coarse level to global (inner threads only; float4)
    if (inner) {
        float* cop = coarse_out + (size_t)img * Hc * Wc;
        *(float4*)(cop + (size_t)ci0 * Wc + cj0) =
            make_float4(acc0[0], acc0[1], acc0[2], acc0[3]);
        *(float4*)(cop + (size_t)(ci0 + 1) * Wc + cj0) =
            make_float4(acc1[0], acc1[1], acc1[2], acc1[3]);
    }

    __syncthreads();

    // ---- stage 2: laplacian. Coarse from SMEM; fine re-read (L1-resident). ----
    if (inner) {
        float c4[4][6];
#pragma unroll
        for (int r = 0; r < 4; r++)
#pragma unroll
            for (int k = 0; k < 6; k++)
                c4[r][k] = sc[(2 * iy - 1) + r][(4 * gx - 1) + k];

        float* lop = lap_out + (size_t)img * H * W;

#pragma unroll
        for (int p = 0; p < 2; p++) {          // coarse row ci0 + p
            float rowE[6], rowO[6];
#pragma unroll
            for (int k = 0; k < 6; k++) {
                rowE[k] = fmaf(0.75f, c4[p + 1][k], 0.125f * (c4[p][k] + c4[p + 2][k]));
                rowO[k] = 0.5f * (c4[p + 1][k] + c4[p + 2][k]);
            }
            float oE[8], oO[8];
#pragma unroll
            for (int t = 0; t < 4; t++) {
                oE[2 * t]     = fmaf(0.75f, rowE[t + 1], 0.125f * (rowE[t] + rowE[t + 2]));
                oE[2 * t + 1] = 0.5f * (rowE[t + 1] + rowE[t + 2]);
                oO[2 * t]     = fmaf(0.75f, rowO[t + 1], 0.125f * (rowO[t] + rowO[t + 2]));
                oO[2 * t + 1] = 0.5f * (rowO[t + 1] + rowO[t + 2]);
            }

            size_t top = (size_t)(2 * (ci0 + p)) * W + 2 * cj0;
            size_t bot = top + W;

            float4 fT0 = *(const float4*)(fp + top);
            float4 fT1 = *(const float4*)(fp + top + 4);
            float4 fB0 = *(const float4*)(fp + bot);
            float4 fB1 = *(const float4*)(fp + bot + 4);

            __stcs((float4*)(lop + top),
                   make_float4(fT0.x - oE[0], fT0.y - oE[1], fT0.z - oE[2], fT0.w - oE[3]));
            __stcs((float4*)(lop + top + 4),
                   make_float4(fT1.x - oE[4], fT1.y - oE[5], fT1.z - oE[6], fT1.w - oE[7]));
            __stcs((float4*)(lop + bot),
                   make_float4(fB0.x - oO[0], fB0.y - oO[1], fB0.z - oO[2], fB0.w - oO[3]));
            __stcs((float4*)(lop + bot + 4),
                   make_float4(fB1.x - oO[4], fB1.y - oO[5], fB1.z - oO[6], fB1.w - oO[7]));
        }
    }
}

extern "C" void kernel_launch(void* const* d_in, const int* in_sizes, int n_in,
                              void* d_out, int out_size) {
    const float* im = (const float*)d_in[0];
    float* out = (float*)d_out;

    float* g1; float* g2; float* g3;
    cudaGetSymbolAddress((void**)&g1, g_g1);
    cudaGetSymbolAddress((void**)&g2, g_g2);
    cudaGetSymbolAddress((void**)&g3, g_g3);

    const long long off0 = 0;
    const long long off1 = off0 + (long long)NIMG * 1024 * 1024;
    const long long off2 = off1 + (long long)NIMG * 512 * 512;
    const long long off3 = off2 + (long long)NIMG * 256 * 256;
    const long long off4 = off3 + (long long)NIMG * 128 * 128;

    // level l: fine = g_l, writes g_{l+1} and lap_l
    {
        dim3 grid(512 / 64, 512 / 32, NIMG);   // coarse 512x512, tile 32x64
        fused_level_kernel<512, 512, 32><<<grid, dim3(18, 18)>>>(im, g1, out + off0);
    }
    {
        dim3 grid(256 / 64, 256 / 32, NIMG);   // coarse 256x256
        fused_level_kernel<256, 256, 32><<<grid, dim3(18, 18)>>>(g1, g2, out + off1);
    }
    {
        dim3 grid(128 / 64, 128 / 16, NIMG);   // coarse 128x128, tile 16x64
        fused_level_kernel<128, 128, 16><<<grid, dim3(18, 10)>>>(g2, g3, out + off2);
    }
    {
        dim3 grid(64 / 64, 64 / 16, NIMG);     // coarse 64x64; g4 = lpyr[4]
        fused_level_kernel<64, 64, 16><<<grid, dim3(18, 10)>>>(g3, out + off4, out + off3);
    }
}